// round 10
// baseline (speedup 1.0000x reference)
#include <cuda_runtime.h>

#define NB 32
#define NC 2
#define NL 262144
#define NT 1024
#define ND 512
#define NHOP 256
#define NF 257
#define PADL 128
#define TT 16
#define AMINF 1e-10f
#define TEN_OVER_LOG2_10 3.0102999566398120f  // 10 / log2(10)

typedef unsigned long long u64;

// Pre-packed folded DFT kernels: rows d=0..255, 256 f-cols, stride 256 (16B aligned)
__device__ float g_krp[256 * 256];
__device__ float g_kip[256 * 256];
__device__ unsigned int g_pmax;

#define PACK2(dst, v) \
    asm("mov.b64 %0, {%1, %1};" : "=l"(dst) : "r"(__float_as_uint(v)))
#define FMA2(acc, ka, sb) \
    asm("fma.rn.f32x2 %0, %1, %2, %0;" : "+l"(acc) : "l"(ka), "l"(sb))
#define UNPACK2(lo, hi, v) \
    asm("mov.b64 {%0, %1}, %2;" : "=r"(lo), "=r"(hi) : "l"(v))

// ---------------------------------------------------------------------------
__global__ void prep_kernel(const float* __restrict__ kre,
                            const float* __restrict__ kim) {
    int i = blockIdx.x * 256 + threadIdx.x;  // 0..65535
    int d = i >> 8, f = i & 255;
    g_krp[i] = kre[d * NF + f];
    g_kip[i] = kim[d * NF + f];
    if (i == 0) g_pmax = 0u;
}

// ---------------------------------------------------------------------------
// Main folded-DFT GEMM with packed FFMA2. grid = (NT/TT, NC, NB), block 256.
// Thread tile: 4 f (as 2 f32x2 pairs) x 4 frames, re+im.
// ---------------------------------------------------------------------------
__global__ __launch_bounds__(256) void spec_main(const float* __restrict__ x,
                                                 const float* __restrict__ kre,
                                                 float* __restrict__ out) {
    __shared__ float ss[256 * TT];  // s[d][t] = x[d]+x[512-d]
    __shared__ float sa[256 * TT];  // a[d][t] = x[d]-x[512-d]
    __shared__ float xmid[TT];      // x[256] per frame
    __shared__ float red[8];

    const int tid = threadIdx.x;
    const int bx = blockIdx.x, c = blockIdx.y, b = blockIdx.z;
    const float* xin = x + (size_t)(b * NC + c) * NL;
    const int tbase = bx * TT;
    const int gbase = tbase * NHOP - PADL;

    for (int e = tid; e < 256 * TT; e += 256) {
        int d = e & 255;
        int t = e >> 8;
        if (d) {
            int g1 = gbase + t * NHOP + d;
            int g2 = gbase + t * NHOP + ND - d;
            float u = (g1 >= 0 && g1 < NL) ? xin[g1] : 0.f;
            float v = (g2 >= 0 && g2 < NL) ? xin[g2] : 0.f;
            ss[d * TT + t] = u + v;
            sa[d * TT + t] = u - v;
        }
    }
    if (tid < TT) {
        int g = gbase + tid * NHOP + NHOP;
        xmid[tid] = (g >= 0 && g < NL) ? xin[g] : 0.f;
    }
    __syncthreads();

    const int fi = tid & 63, ti = tid >> 6;
    const int f0 = fi * 4, tt0 = ti * 4;

    u64 aR[2][4], aI[2][4];
#pragma unroll
    for (int p = 0; p < 2; p++)
#pragma unroll
        for (int j = 0; j < 4; j++) { aR[p][j] = 0ull; aI[p][j] = 0ull; }

#pragma unroll 2
    for (int d = 1; d < 256; d++) {
        // k pairs: (k_f0,k_f0+1), (k_f0+2,k_f0+3) directly from float4 layout
        ulonglong2 kr2 = *(const ulonglong2*)&g_krp[d * 256 + f0];
        ulonglong2 ki2 = *(const ulonglong2*)&g_kip[d * 256 + f0];
        float4 sv = *(const float4*)&ss[d * TT + tt0];
        float4 av = *(const float4*)&sa[d * TT + tt0];
        u64 s2[4], a2[4];
        PACK2(s2[0], sv.x); PACK2(s2[1], sv.y);
        PACK2(s2[2], sv.z); PACK2(s2[3], sv.w);
        PACK2(a2[0], av.x); PACK2(a2[1], av.y);
        PACK2(a2[2], av.z); PACK2(a2[3], av.w);
#pragma unroll
        for (int j = 0; j < 4; j++) {
            FMA2(aR[0][j], kr2.x, s2[j]);
            FMA2(aR[1][j], kr2.y, s2[j]);
            FMA2(aI[0][j], ki2.x, a2[j]);
            FMA2(aI[1][j], ki2.y, a2[j]);
        }
    }

    // d=256 re term (k_imag[256] ~ 0), power -> log, track max power.
    float krm[4];
#pragma unroll
    for (int i = 0; i < 4; i++) krm[i] = __ldg(&kre[256 * NF + f0 + i]);

    float pmax = 0.f;
#pragma unroll
    for (int p = 0; p < 2; p++)
#pragma unroll
        for (int j = 0; j < 4; j++) {
            unsigned rlo_u, rhi_u, ilo_u, ihi_u;
            UNPACK2(rlo_u, rhi_u, aR[p][j]);
            UNPACK2(ilo_u, ihi_u, aI[p][j]);
            float xm = xmid[tt0 + j];
            int t = tbase + tt0 + j;
#pragma unroll
            for (int h = 0; h < 2; h++) {
                int fofs = 2 * p + h;
                float re = fmaf(xm, krm[fofs],
                                __uint_as_float(h ? rhi_u : rlo_u));
                float im = __uint_as_float(h ? ihi_u : ilo_u);
                float pw = fmaxf(fmaf(re, re, im * im), AMINF);
                pmax = fmaxf(pmax, pw);
                float lp = TEN_OVER_LOG2_10 * __log2f(pw);
                int f = f0 + fofs;
                out[(((size_t)b * NF + f) * NT + t) * NC + c] = lp;
            }
        }

#pragma unroll
    for (int o = 16; o; o >>= 1)
        pmax = fmaxf(pmax, __shfl_xor_sync(0xFFFFFFFFu, pmax, o));
    if ((tid & 31) == 0) red[tid >> 5] = pmax;
    __syncthreads();
    if (tid == 0) {
        float m = red[0];
#pragma unroll
        for (int w = 1; w < 8; w++) m = fmaxf(m, red[w]);
        atomicMax(&g_pmax, __float_as_uint(m));
    }
}

// ---------------------------------------------------------------------------
// Nyquist column f=256. grid = (NT/8, NC, NB), block 256.
// ---------------------------------------------------------------------------
__global__ void spec_nyq(const float* __restrict__ x,
                         const float* __restrict__ kre,
                         float* __restrict__ out) {
    const int tid = threadIdx.x, lane = tid & 31, w = tid >> 5;
    const int c = blockIdx.y, b = blockIdx.z;
    const int t = blockIdx.x * 8 + w;
    const float* xin = x + (size_t)(b * NC + c) * NL;
    const int gb = t * NHOP - PADL;
    float re = 0.f;
#pragma unroll 4
    for (int d = lane; d < ND; d += 32) {
        int g = gb + d;
        float xv = (g >= 0 && g < NL) ? xin[g] : 0.f;
        re = fmaf(xv, __ldg(&kre[d * NF + 256]), re);
    }
#pragma unroll
    for (int o = 16; o; o >>= 1) re += __shfl_xor_sync(0xFFFFFFFFu, re, o);
    __shared__ float pm[8];
    if (lane == 0) {
        float p = fmaxf(re * re, AMINF);
        out[(((size_t)b * NF + 256) * NT + t) * NC + c] =
            TEN_OVER_LOG2_10 * __log2f(p);
        pm[w] = p;
    }
    __syncthreads();
    if (tid == 0) {
        float m = pm[0];
#pragma unroll
        for (int i = 1; i < 8; i++) m = fmaxf(m, pm[i]);
        atomicMax(&g_pmax, __float_as_uint(m));
    }
}

// ---------------------------------------------------------------------------
__global__ void spec_fin(float* __restrict__ out, int n4) {
    int i = blockIdx.x * 256 + threadIdx.x;
    if (i >= n4) return;
    float lmax =
        TEN_OVER_LOG2_10 * __log2f(fmaxf(__uint_as_float(g_pmax), AMINF));
    float4 v = ((float4*)out)[i];
    v.x = fmaxf(v.x - lmax, -80.f);
    v.y = fmaxf(v.y - lmax, -80.f);
    v.z = fmaxf(v.z - lmax, -80.f);
    v.w = fmaxf(v.w - lmax, -80.f);
    ((float4*)out)[i] = v;
}

extern "C" void kernel_launch(void* const* d_in, const int* in_sizes, int n_in,
                              void* d_out, int out_size) {
    const float* x = (const float*)d_in[0];
    const float* kre = (const float*)d_in[1];
    const float* kim = (const float*)d_in[2];
    float* out = (float*)d_out;

    prep_kernel<<<256, 256>>>(kre, kim);

    dim3 gmain(NT / TT, NC, NB);
    spec_main<<<gmain, 256>>>(x, kre, out);

    dim3 gnyq(NT / 8, NC, NB);
    spec_nyq<<<gnyq, 256>>>(x, kre, out);

    int n4 = out_size / 4;
    spec_fin<<<(n4 + 255) / 256, 256>>>(out, n4);
}

// round 12
// speedup vs baseline: 1.4762x; 1.4762x over previous
#include <cuda_runtime.h>
#include <cuda_bf16.h>

#define NB 32
#define NC 2
#define NL 262144
#define NT 1024
#define NF 257
#define AMINF 1e-10f
#define TEN_OVER_LOG2_10 3.0102999566398120f

#define MFR 65536   // total frames
#define KD  512     // GEMM K
#define KC  64      // K chunk (bf16 elements)

// smem geometry: 4 tiles x 128 rows x 72 halves (144B row stride), double buffered
#define ROWB   144
#define TILEB  (128 * ROWB)          // 18432
#define T_AHI  0
#define T_ALO  TILEB
#define T_BHI  (2 * TILEB)
#define T_BLO  (3 * TILEB)
#define BUFB   (4 * TILEB)           // 73728
#define SMEM_TOTAL (2 * BUFB)        // 147456

// ---- scratch ----
__device__ unsigned short g_Ahi[(size_t)MFR * KD];   // 64 MB
__device__ unsigned short g_Alo[(size_t)MFR * KD];   // 64 MB
__device__ unsigned short g_Bhi[512 * KD];           // interleaved rows: 2f=re_f, 2f+1=im_f
__device__ unsigned short g_Blo[512 * KD];
__device__ float g_P[(size_t)64 * NF * NT];          // log-power scratch [bc][f][t], 67 MB
__device__ unsigned int g_pmax;

// ---- helpers ----
__device__ __forceinline__ unsigned smem_u32(const void* p) {
    unsigned a;
    asm("{ .reg .u64 t; cvta.to.shared.u64 t, %1; cvt.u32.u64 %0, t; }"
        : "=r"(a) : "l"(p));
    return a;
}
#define CP16(dst, src) \
    asm volatile("cp.async.cg.shared.global [%0], [%1], 16;" :: "r"(dst), "l"(src))
#define CPCOMMIT() asm volatile("cp.async.commit_group;" ::: "memory")
#define CPWAIT(n)  asm volatile("cp.async.wait_group %0;" :: "n"(n) : "memory")

__device__ __forceinline__ void ldsm4(unsigned* r, unsigned addr) {
    asm volatile("ldmatrix.sync.aligned.m8n8.x4.shared.b16 {%0,%1,%2,%3}, [%4];"
                 : "=r"(r[0]), "=r"(r[1]), "=r"(r[2]), "=r"(r[3]) : "r"(addr));
}
__device__ __forceinline__ void ldsm2(unsigned* r, unsigned addr) {
    asm volatile("ldmatrix.sync.aligned.m8n8.x2.shared.b16 {%0,%1}, [%2];"
                 : "=r"(r[0]), "=r"(r[1]) : "r"(addr));
}
__device__ __forceinline__ void mma_bf16(float* d, const unsigned* a,
                                         const unsigned* b) {
    asm volatile(
        "mma.sync.aligned.m16n8k16.row.col.f32.bf16.bf16.f32 "
        "{%0,%1,%2,%3}, {%4,%5,%6,%7}, {%8,%9}, {%0,%1,%2,%3};"
        : "+f"(d[0]), "+f"(d[1]), "+f"(d[2]), "+f"(d[3])
        : "r"(a[0]), "r"(a[1]), "r"(a[2]), "r"(a[3]), "r"(b[0]), "r"(b[1]));
}

// ---------------------------------------------------------------------------
// prep_B: bf16 hi/lo B, rows interleaved (2f -> k_real bin f, 2f+1 -> k_imag).
// grid = 1024 x 256.
// ---------------------------------------------------------------------------
__global__ void prep_B(const float* __restrict__ kre,
                       const float* __restrict__ kim) {
    int i = blockIdx.x * 256 + threadIdx.x;  // 0..262143
    int n = i >> 9, k = i & 511;
    int f = n >> 1;
    float v = (n & 1) ? kim[(size_t)k * NF + f] : kre[(size_t)k * NF + f];
    __nv_bfloat16 h = __float2bfloat16(v);
    __nv_bfloat16 l = __float2bfloat16(v - __bfloat162float(h));
    g_Bhi[(size_t)n * KD + k] = __bfloat16_as_ushort(h);
    g_Blo[(size_t)n * KD + k] = __bfloat16_as_ushort(l);
    if (i == 0) g_pmax = 0u;
}

// ---------------------------------------------------------------------------
// prep_A: frame extraction -> bf16 hi/lo scratch [MFR x 512]. grid = 16384x256.
// ---------------------------------------------------------------------------
__global__ void prep_A(const float* __restrict__ x) {
    int idx = blockIdx.x * 256 + threadIdx.x;
    int m = idx >> 6;
    int d0 = (idx & 63) << 3;
    int t = m & (NT - 1);
    int bc = m >> 10;
    const float* xp = x + (size_t)bc * NL;
    int g0 = t * 256 + d0 - 128;
    float v[8];
    if (g0 >= 0 && g0 + 8 <= NL) {
        float4 u0 = *(const float4*)(xp + g0);
        float4 u1 = *(const float4*)(xp + g0 + 4);
        v[0] = u0.x; v[1] = u0.y; v[2] = u0.z; v[3] = u0.w;
        v[4] = u1.x; v[5] = u1.y; v[6] = u1.z; v[7] = u1.w;
    } else {
#pragma unroll
        for (int j = 0; j < 8; j++) {
            int g = g0 + j;
            v[j] = (g >= 0 && g < NL) ? xp[g] : 0.f;
        }
    }
    unsigned hw[4], lw[4];
#pragma unroll
    for (int j = 0; j < 4; j++) {
        __nv_bfloat16 h0 = __float2bfloat16(v[2 * j]);
        __nv_bfloat16 h1 = __float2bfloat16(v[2 * j + 1]);
        __nv_bfloat16 l0 = __float2bfloat16(v[2 * j] - __bfloat162float(h0));
        __nv_bfloat16 l1 = __float2bfloat16(v[2 * j + 1] - __bfloat162float(h1));
        hw[j] = (unsigned)__bfloat16_as_ushort(h0) |
                ((unsigned)__bfloat16_as_ushort(h1) << 16);
        lw[j] = (unsigned)__bfloat16_as_ushort(l0) |
                ((unsigned)__bfloat16_as_ushort(l1) << 16);
    }
    size_t off = (size_t)m * KD + d0;
    *(uint4*)(g_Ahi + off) = make_uint4(hw[0], hw[1], hw[2], hw[3]);
    *(uint4*)(g_Alo + off) = make_uint4(lw[0], lw[1], lw[2], lw[3]);
}

// ---------------------------------------------------------------------------
// spec_gemm: CTA tile 128(m) x 128(n), K=512 in 8 chunks, cp.async double buf.
// 3 compensated bf16 products via mma.sync m16n8k16. 8 warps: 2(m) x 4(n),
// warp tile 64x32. grid = (4 ntiles, 512 mtiles).
// ---------------------------------------------------------------------------
__global__ __launch_bounds__(256) void spec_gemm(float* __restrict__ P) {
    extern __shared__ char smem[];
    const unsigned sb = smem_u32(smem);
    const int tid = threadIdx.x;
    const int wid = tid >> 5, lane = tid & 31;
    const int warp_m = wid >> 2, warp_n = wid & 3;
    const int m0 = blockIdx.y * 128, n0 = blockIdx.x * 128;

    float d[4][4][4];
#pragma unroll
    for (int mi = 0; mi < 4; mi++)
#pragma unroll
        for (int ni = 0; ni < 4; ni++)
#pragma unroll
            for (int r = 0; r < 4; r++) d[mi][ni][r] = 0.f;

    // per-thread ldmatrix base offsets (bytes within a tile)
    const unsigned a_base = (unsigned)((warp_m * 64 + (lane & 15)) * ROWB +
                                       ((lane >> 4) << 4));
    const unsigned b_base = (unsigned)((warp_n * 32 + (lane & 7)) * ROWB +
                                       (((lane >> 3) & 1) << 4));

    // ---- staging (16 cp.async of 16B per thread per chunk) ----
    auto stage = [&](int buf, int ch) {
        const int k0 = ch * KC;
#pragma unroll
        for (int rep = 0; rep < 16; rep++) {
            int i = rep * 256 + tid;
            int tile = i >> 10, row = (i >> 3) & 127, seg = i & 7;
            const unsigned short* src;
            if (tile == 0)      src = g_Ahi + ((size_t)(m0 + row) * KD + k0);
            else if (tile == 1) src = g_Alo + ((size_t)(m0 + row) * KD + k0);
            else if (tile == 2) src = g_Bhi + ((size_t)(n0 + row) * KD + k0);
            else                src = g_Blo + ((size_t)(n0 + row) * KD + k0);
            unsigned dst = sb + buf * BUFB + tile * TILEB + row * ROWB + seg * 16;
            CP16(dst, src + seg * 8);
        }
        CPCOMMIT();
    };

    stage(0, 0);
    for (int ch = 0; ch < 8; ch++) {
        const int buf = ch & 1;
        if (ch < 7) { stage(buf ^ 1, ch + 1); CPWAIT(1); }
        else        { CPWAIT(0); }
        __syncthreads();

#pragma unroll
        for (int pass = 0; pass < 3; pass++) {
            const unsigned at = (pass == 2) ? T_ALO : T_AHI;
            const unsigned bt = (pass == 1) ? T_BLO : T_BHI;
            const unsigned abase = sb + buf * BUFB + at + a_base;
            const unsigned bbase = sb + buf * BUFB + bt + b_base;
#pragma unroll
            for (int ks = 0; ks < 4; ks++) {
                unsigned a[4][4], bf[4][2];
#pragma unroll
                for (int mi = 0; mi < 4; mi++)
                    ldsm4(a[mi], abase + mi * (16 * ROWB) + ks * 32);
#pragma unroll
                for (int ni = 0; ni < 4; ni++)
                    ldsm2(bf[ni], bbase + ni * (8 * ROWB) + ks * 32);
#pragma unroll
                for (int mi = 0; mi < 4; mi++)
#pragma unroll
                    for (int ni = 0; ni < 4; ni++)
                        mma_bf16(d[mi][ni], a[mi], bf[ni]);
            }
        }
        __syncthreads();
    }

    // ---- epilogue: col pairs are (re_f, im_f); write log-power to g_P ----
    float pmax = 0.f;
    const int fbase = (n0 >> 1) + warp_n * 16 + (lane & 3);
#pragma unroll
    for (int mi = 0; mi < 4; mi++) {
        int mrow = m0 + warp_m * 64 + mi * 16 + (lane >> 2);
#pragma unroll
        for (int h = 0; h < 2; h++) {
            int m = mrow + h * 8;
            int bc = m >> 10, t = m & (NT - 1);
#pragma unroll
            for (int ni = 0; ni < 4; ni++) {
                float re = d[mi][ni][2 * h];
                float im = d[mi][ni][2 * h + 1];
                float p = fmaxf(fmaf(re, re, im * im), AMINF);
                pmax = fmaxf(pmax, p);
                int f = fbase + ni * 4;
                g_P[((size_t)bc * NF + f) * NT + t] =
                    TEN_OVER_LOG2_10 * __log2f(p);
            }
        }
    }
#pragma unroll
    for (int o = 16; o; o >>= 1)
        pmax = fmaxf(pmax, __shfl_xor_sync(0xFFFFFFFFu, pmax, o));
    __shared__ float red[8];
    if (lane == 0) red[wid] = pmax;
    __syncthreads();
    if (tid == 0) {
        float mm = red[0];
#pragma unroll
        for (int w = 1; w < 8; w++) mm = fmaxf(mm, red[w]);
        atomicMax(&g_pmax, __float_as_uint(mm));
    }
}

// ---------------------------------------------------------------------------
// Nyquist bin f=256 (k_imag[:,256] == 0), fp32 -> g_P. grid=(NT/8, NC, NB).
// ---------------------------------------------------------------------------
__global__ void spec_nyq(const float* __restrict__ x,
                         const float* __restrict__ kre) {
    const int tid = threadIdx.x, lane = tid & 31, w = tid >> 5;
    const int c = blockIdx.y, b = blockIdx.z;
    const int t = blockIdx.x * 8 + w;
    const float* xin = x + (size_t)(b * NC + c) * NL;
    const int gb = t * 256 - 128;
    float re = 0.f;
#pragma unroll 4
    for (int dd = lane; dd < KD; dd += 32) {
        int g = gb + dd;
        float xv = (g >= 0 && g < NL) ? xin[g] : 0.f;
        re = fmaf(xv, __ldg(&kre[dd * NF + 256]), re);
    }
#pragma unroll
    for (int o = 16; o; o >>= 1) re += __shfl_xor_sync(0xFFFFFFFFu, re, o);
    __shared__ float pm[8];
    if (lane == 0) {
        float p = fmaxf(re * re, AMINF);
        g_P[((size_t)(b * NC + c) * NF + 256) * NT + t] =
            TEN_OVER_LOG2_10 * __log2f(p);
        pm[w] = p;
    }
    __syncthreads();
    if (tid == 0) {
        float m = pm[0];
#pragma unroll
        for (int i = 1; i < 8; i++) m = fmaxf(m, pm[i]);
        atomicMax(&g_pmax, __float_as_uint(m));
    }
}

// ---------------------------------------------------------------------------
// spec_fin: transpose-interleave g_P[bc][f][t] -> out[b][f][t][c], subtract
// global max, clamp. One block per (b,f) row: fully coalesced both sides.
// ---------------------------------------------------------------------------
__global__ void spec_fin(float* __restrict__ out) {
    const int bf = blockIdx.x;          // 0..32*257-1
    const int b = bf / NF, f = bf % NF;
    const float lmax =
        TEN_OVER_LOG2_10 * __log2f(fmaxf(__uint_as_float(g_pmax), AMINF));
    const float* s0 = g_P + ((size_t)(b * 2 + 0) * NF + f) * NT;
    const float* s1 = g_P + ((size_t)(b * 2 + 1) * NF + f) * NT;
    float2* orow = (float2*)(out + ((size_t)b * NF + f) * NT * NC);
#pragma unroll
    for (int j = 0; j < 4; j++) {
        int t = j * 256 + threadIdx.x;
        float2 v;
        v.x = fmaxf(s0[t] - lmax, -80.f);
        v.y = fmaxf(s1[t] - lmax, -80.f);
        orow[t] = v;
    }
}

extern "C" void kernel_launch(void* const* d_in, const int* in_sizes, int n_in,
                              void* d_out, int out_size) {
    const float* x = (const float*)d_in[0];
    const float* kre = (const float*)d_in[1];
    const float* kim = (const float*)d_in[2];
    float* out = (float*)d_out;

    cudaFuncSetAttribute(spec_gemm, cudaFuncAttributeMaxDynamicSharedMemorySize,
                         SMEM_TOTAL);

    prep_B<<<1024, 256>>>(kre, kim);
    prep_A<<<16384, 256>>>(x);

    float* P;
    cudaGetSymbolAddress((void**)&P, g_P);
    spec_gemm<<<dim3(4, MFR / 128), 256, SMEM_TOTAL>>>(P);
    spec_nyq<<<dim3(NT / 8, NC, NB), 256>>>(x, kre);
    spec_fin<<<NB * NF, 256>>>(out);
}

// round 14
// speedup vs baseline: 2.1579x; 1.4617x over previous
#include <cuda_runtime.h>
#include <cuda_fp16.h>

#define NB 32
#define NC 2
#define NL 262144
#define NT 1024
#define NF 257
#define AMINF 1e-10f
#define TEN_OVER_LOG2_10 3.0102999566398120f

#define MFR 65536   // total frames
#define KD  512     // GEMM K
#define KC  64      // K chunk (fp16 elements)

// smem geometry: 3 tiles (A, Bhi, Blo) x 128 rows x 144B stride, double buffered
#define ROWB   144
#define TILEB  (128 * ROWB)          // 18432
#define T_A    0
#define T_BHI  TILEB
#define T_BLO  (2 * TILEB)
#define BUFB   (3 * TILEB)           // 55296
#define SMEM_TOTAL (2 * BUFB)        // 110592 -> 2 CTAs/SM

// ---- scratch ----
__device__ unsigned short g_Ah[(size_t)MFR * KD];    // 64 MB, fp16 frames
__device__ unsigned short g_Bhi[512 * KD];           // rows: 2f=re_f, 2f+1=im_f; row1 = re_256
__device__ unsigned short g_Blo[512 * KD];
__device__ float g_P[(size_t)64 * NF * NT];          // log-power scratch [bc][f][t]
__device__ unsigned int g_pmax;

// ---- helpers ----
__device__ __forceinline__ unsigned smem_u32(const void* p) {
    unsigned a;
    asm("{ .reg .u64 t; cvta.to.shared.u64 t, %1; cvt.u32.u64 %0, t; }"
        : "=r"(a) : "l"(p));
    return a;
}
#define CP16(dst, src) \
    asm volatile("cp.async.cg.shared.global [%0], [%1], 16;" :: "r"(dst), "l"(src))
#define CPCOMMIT() asm volatile("cp.async.commit_group;" ::: "memory")
#define CPWAIT(n)  asm volatile("cp.async.wait_group %0;" :: "n"(n) : "memory")

__device__ __forceinline__ void ldsm4(unsigned* r, unsigned addr) {
    asm volatile("ldmatrix.sync.aligned.m8n8.x4.shared.b16 {%0,%1,%2,%3}, [%4];"
                 : "=r"(r[0]), "=r"(r[1]), "=r"(r[2]), "=r"(r[3]) : "r"(addr));
}
__device__ __forceinline__ void mma_fp16(float* d, const unsigned* a,
                                         const unsigned* b) {
    asm volatile(
        "mma.sync.aligned.m16n8k16.row.col.f32.f16.f16.f32 "
        "{%0,%1,%2,%3}, {%4,%5,%6,%7}, {%8,%9}, {%0,%1,%2,%3};"
        : "+f"(d[0]), "+f"(d[1]), "+f"(d[2]), "+f"(d[3])
        : "r"(a[0]), "r"(a[1]), "r"(a[2]), "r"(a[3]), "r"(b[0]), "r"(b[1]));
}

// ---------------------------------------------------------------------------
// prep_B: fp16 hi/lo B. Row n=2f -> k_real bin f, n=2f+1 -> k_imag bin f,
// EXCEPT row 1 (im_0 == 0) carries re of the Nyquist bin f=256.
// ---------------------------------------------------------------------------
__global__ void prep_B(const float* __restrict__ kre,
                       const float* __restrict__ kim) {
    int i = blockIdx.x * 256 + threadIdx.x;  // 0..262143
    int n = i >> 9, k = i & 511;
    int f = n >> 1;
    float v;
    if (n == 1)       v = kre[(size_t)k * NF + 256];
    else if (n & 1)   v = kim[(size_t)k * NF + f];
    else              v = kre[(size_t)k * NF + f];
    __half h = __float2half_rn(v);
    __half l = __float2half_rn(v - __half2float(h));
    g_Bhi[(size_t)n * KD + k] = __half_as_ushort(h);
    g_Blo[(size_t)n * KD + k] = __half_as_ushort(l);
    if (i == 0) g_pmax = 0u;
}

// ---------------------------------------------------------------------------
// prep_A: frame extraction -> fp16 scratch [MFR x 512].
// ---------------------------------------------------------------------------
__global__ void prep_A(const float* __restrict__ x) {
    int idx = blockIdx.x * 256 + threadIdx.x;
    int m = idx >> 6;
    int d0 = (idx & 63) << 3;
    int t = m & (NT - 1);
    int bc = m >> 10;
    const float* xp = x + (size_t)bc * NL;
    int g0 = t * 256 + d0 - 128;
    float v[8];
    if (g0 >= 0 && g0 + 8 <= NL) {
        float4 u0 = *(const float4*)(xp + g0);
        float4 u1 = *(const float4*)(xp + g0 + 4);
        v[0] = u0.x; v[1] = u0.y; v[2] = u0.z; v[3] = u0.w;
        v[4] = u1.x; v[5] = u1.y; v[6] = u1.z; v[7] = u1.w;
    } else {
#pragma unroll
        for (int j = 0; j < 8; j++) {
            int g = g0 + j;
            v[j] = (g >= 0 && g < NL) ? xp[g] : 0.f;
        }
    }
    unsigned hw[4];
#pragma unroll
    for (int j = 0; j < 4; j++) {
        __half h0 = __float2half_rn(v[2 * j]);
        __half h1 = __float2half_rn(v[2 * j + 1]);
        hw[j] = (unsigned)__half_as_ushort(h0) |
                ((unsigned)__half_as_ushort(h1) << 16);
    }
    *(uint4*)(g_Ah + (size_t)m * KD + d0) = make_uint4(hw[0], hw[1], hw[2], hw[3]);
}

// ---------------------------------------------------------------------------
// spec_gemm: CTA tile 128(m) x 128(n), K=512 in 8 chunks, cp.async double buf.
// 2 passes: A*Bhi + A*Blo (fp16, fp32 accum). 8 warps 2(m)x4(n), warp 64x32.
// grid = (4 ntiles, 512 mtiles); 110.6 KB smem -> 2 CTAs/SM.
// ---------------------------------------------------------------------------
__global__ __launch_bounds__(256) void spec_gemm(float* __restrict__ P) {
    extern __shared__ char smem[];
    const unsigned sb = smem_u32(smem);
    const int tid = threadIdx.x;
    const int wid = tid >> 5, lane = tid & 31;
    const int warp_m = wid >> 2, warp_n = wid & 3;
    const int m0 = blockIdx.y * 128, n0 = blockIdx.x * 128;

    float d[4][4][4];
#pragma unroll
    for (int mi = 0; mi < 4; mi++)
#pragma unroll
        for (int ni = 0; ni < 4; ni++)
#pragma unroll
            for (int r = 0; r < 4; r++) d[mi][ni][r] = 0.f;

    const unsigned a_base = (unsigned)((warp_m * 64 + (lane & 15)) * ROWB +
                                       ((lane >> 4) << 4));
    // x4 B: lanes 0-7 n+0..7/seg0, 8-15 n+0..7/seg1, 16-23 n+8..15/seg0, 24-31 seg1
    const unsigned b_base = (unsigned)((warp_n * 32 + (lane & 7) +
                                        ((lane >> 4) << 3)) * ROWB +
                                       (((lane >> 3) & 1) << 4));

    auto stage = [&](int buf, int ch) {
        const int k0 = ch * KC;
#pragma unroll
        for (int rep = 0; rep < 12; rep++) {
            int i = rep * 256 + tid;         // 0..3071
            int tile = i >> 10, row = (i >> 3) & 127, seg = i & 7;
            const unsigned short* src;
            if (tile == 0)      src = g_Ah + ((size_t)(m0 + row) * KD + k0);
            else if (tile == 1) src = g_Bhi + ((size_t)(n0 + row) * KD + k0);
            else                src = g_Blo + ((size_t)(n0 + row) * KD + k0);
            unsigned dst = sb + buf * BUFB + tile * TILEB + row * ROWB + seg * 16;
            CP16(dst, src + seg * 8);
        }
        CPCOMMIT();
    };

    stage(0, 0);
    for (int ch = 0; ch < 8; ch++) {
        const int buf = ch & 1;
        if (ch < 7) { stage(buf ^ 1, ch + 1); CPWAIT(1); }
        else        { CPWAIT(0); }
        __syncthreads();

#pragma unroll
        for (int pass = 0; pass < 2; pass++) {
            const unsigned abase = sb + buf * BUFB + T_A + a_base;
            const unsigned bbase =
                sb + buf * BUFB + (pass ? T_BLO : T_BHI) + b_base;
#pragma unroll
            for (int ks = 0; ks < 4; ks++) {
                unsigned a[4][4], bf[4][2];
#pragma unroll
                for (int mi = 0; mi < 4; mi++)
                    ldsm4(a[mi], abase + mi * (16 * ROWB) + ks * 32);
#pragma unroll
                for (int nh = 0; nh < 2; nh++) {
                    unsigned r[4];
                    ldsm4(r, bbase + nh * (16 * ROWB) + ks * 32);
                    bf[2 * nh][0] = r[0]; bf[2 * nh][1] = r[1];
                    bf[2 * nh + 1][0] = r[2]; bf[2 * nh + 1][1] = r[3];
                }
#pragma unroll
                for (int mi = 0; mi < 4; mi++)
#pragma unroll
                    for (int ni = 0; ni < 4; ni++)
                        mma_fp16(d[mi][ni], a[mi], bf[ni]);
            }
        }
        __syncthreads();
    }

    // ---- epilogue: col pairs (re_f, im_f); f==0 pair is (re_0, re_256) ----
    float pmax = 0.f;
    const int fbase = (n0 >> 1) + warp_n * 16 + (lane & 3);
#pragma unroll
    for (int mi = 0; mi < 4; mi++) {
        int mrow = m0 + warp_m * 64 + mi * 16 + (lane >> 2);
#pragma unroll
        for (int h = 0; h < 2; h++) {
            int m = mrow + h * 8;
            int bc = m >> 10, t = m & (NT - 1);
#pragma unroll
            for (int ni = 0; ni < 4; ni++) {
                float re = d[mi][ni][2 * h];
                float im = d[mi][ni][2 * h + 1];
                int f = fbase + ni * 4;
                if (f == 0) {
                    // im slot carries re of Nyquist bin; true im_0 == 0
                    float p0 = fmaxf(re * re, AMINF);
                    float pn = fmaxf(im * im, AMINF);
                    pmax = fmaxf(pmax, fmaxf(p0, pn));
                    g_P[((size_t)bc * NF + 0) * NT + t] =
                        TEN_OVER_LOG2_10 * __log2f(p0);
                    g_P[((size_t)bc * NF + 256) * NT + t] =
                        TEN_OVER_LOG2_10 * __log2f(pn);
                } else {
                    float p = fmaxf(fmaf(re, re, im * im), AMINF);
                    pmax = fmaxf(pmax, p);
                    g_P[((size_t)bc * NF + f) * NT + t] =
                        TEN_OVER_LOG2_10 * __log2f(p);
                }
            }
        }
    }
#pragma unroll
    for (int o = 16; o; o >>= 1)
        pmax = fmaxf(pmax, __shfl_xor_sync(0xFFFFFFFFu, pmax, o));
    __shared__ float red[8];
    if (lane == 0) red[wid] = pmax;
    __syncthreads();
    if (tid == 0) {
        float mm = red[0];
#pragma unroll
        for (int w = 1; w < 8; w++) mm = fmaxf(mm, red[w]);
        atomicMax(&g_pmax, __float_as_uint(mm));
    }
}

// ---------------------------------------------------------------------------
// spec_fin: transpose-interleave g_P[bc][f][t] -> out[b][f][t][c], subtract
// global max, clamp. One block per (b,f) row; coalesced both sides.
// ---------------------------------------------------------------------------
__global__ void spec_fin(float* __restrict__ out) {
    const int bf = blockIdx.x;          // 0..32*257-1
    const int b = bf / NF, f = bf % NF;
    const float lmax =
        TEN_OVER_LOG2_10 * __log2f(fmaxf(__uint_as_float(g_pmax), AMINF));
    const float* s0 = g_P + ((size_t)(b * 2 + 0) * NF + f) * NT;
    const float* s1 = g_P + ((size_t)(b * 2 + 1) * NF + f) * NT;
    float2* orow = (float2*)(out + ((size_t)b * NF + f) * NT * NC);
#pragma unroll
    for (int j = 0; j < 4; j++) {
        int t = j * 256 + threadIdx.x;
        float2 v;
        v.x = fmaxf(s0[t] - lmax, -80.f);
        v.y = fmaxf(s1[t] - lmax, -80.f);
        orow[t] = v;
    }
}

extern "C" void kernel_launch(void* const* d_in, const int* in_sizes, int n_in,
                              void* d_out, int out_size) {
    const float* x = (const float*)d_in[0];
    const float* kre = (const float*)d_in[1];
    const float* kim = (const float*)d_in[2];
    float* out = (float*)d_out;

    cudaFuncSetAttribute(spec_gemm, cudaFuncAttributeMaxDynamicSharedMemorySize,
                         SMEM_TOTAL);

    prep_B<<<1024, 256>>>(kre, kim);
    prep_A<<<16384, 256>>>(x);

    float* P;
    cudaGetSymbolAddress((void**)&P, g_P);
    spec_gemm<<<dim3(4, MFR / 128), 256, SMEM_TOTAL>>>(P);
    spec_fin<<<NB * NF, 256>>>(out);
}

// round 15
// speedup vs baseline: 3.7595x; 1.7423x over previous
#include <cuda_runtime.h>
#include <cuda_fp16.h>

#define NB 32
#define NC 2
#define NL 262144
#define NT 1024
#define NF 257
#define AMINF 1e-10f
#define TEN_OVER_LOG2_10 3.0102999566398120f

#define MFR 65536   // total frames
#define KD  512     // GEMM K
#define KC  64      // K chunk (fp16 elements)

// smem geometry: 2 tiles (A, B) x 128 rows x 144B stride, double buffered
#define ROWB   144
#define TILEB  (128 * ROWB)          // 18432
#define T_A    0
#define T_B    TILEB
#define BUFB   (2 * TILEB)           // 36864
#define SMEM_TOTAL (2 * BUFB)        // 73728 -> 2 CTAs/SM with slack

// ---- scratch ----
__device__ unsigned short g_Ah[(size_t)MFR * KD];    // 64 MB, fp16 frames
__device__ unsigned short g_B[512 * KD];             // rows: 2f=re_f, 2f+1=im_f; row1 = re_256
__device__ float g_P[(size_t)64 * NF * NT];          // log-power scratch [bc][f][t]
__device__ unsigned int g_pmax;

// ---- helpers ----
__device__ __forceinline__ unsigned smem_u32(const void* p) {
    unsigned a;
    asm("{ .reg .u64 t; cvta.to.shared.u64 t, %1; cvt.u32.u64 %0, t; }"
        : "=r"(a) : "l"(p));
    return a;
}
#define CP16(dst, src) \
    asm volatile("cp.async.cg.shared.global [%0], [%1], 16;" :: "r"(dst), "l"(src))
#define CPCOMMIT() asm volatile("cp.async.commit_group;" ::: "memory")
#define CPWAIT(n)  asm volatile("cp.async.wait_group %0;" :: "n"(n) : "memory")

__device__ __forceinline__ void ldsm4(unsigned* r, unsigned addr) {
    asm volatile("ldmatrix.sync.aligned.m8n8.x4.shared.b16 {%0,%1,%2,%3}, [%4];"
                 : "=r"(r[0]), "=r"(r[1]), "=r"(r[2]), "=r"(r[3]) : "r"(addr));
}
__device__ __forceinline__ void mma_fp16(float* d, const unsigned* a,
                                         const unsigned* b) {
    asm volatile(
        "mma.sync.aligned.m16n8k16.row.col.f32.f16.f16.f32 "
        "{%0,%1,%2,%3}, {%4,%5,%6,%7}, {%8,%9}, {%0,%1,%2,%3};"
        : "+f"(d[0]), "+f"(d[1]), "+f"(d[2]), "+f"(d[3])
        : "r"(a[0]), "r"(a[1]), "r"(a[2]), "r"(a[3]), "r"(b[0]), "r"(b[1]));
}

// ---------------------------------------------------------------------------
// prep_B: fp16 B. Row n=2f -> k_real bin f, n=2f+1 -> k_imag bin f,
// EXCEPT row 1 (im_0 == 0) carries re of the Nyquist bin f=256.
// ---------------------------------------------------------------------------
__global__ void prep_B(const float* __restrict__ kre,
                       const float* __restrict__ kim) {
    int i = blockIdx.x * 256 + threadIdx.x;  // 0..262143
    int n = i >> 9, k = i & 511;
    int f = n >> 1;
    float v;
    if (n == 1)       v = kre[(size_t)k * NF + 256];
    else if (n & 1)   v = kim[(size_t)k * NF + f];
    else              v = kre[(size_t)k * NF + f];
    g_B[(size_t)n * KD + k] = __half_as_ushort(__float2half_rn(v));
    if (i == 0) g_pmax = 0u;
}

// ---------------------------------------------------------------------------
// prep_A: frame extraction -> fp16 scratch [MFR x 512].
// ---------------------------------------------------------------------------
__global__ void prep_A(const float* __restrict__ x) {
    int idx = blockIdx.x * 256 + threadIdx.x;
    int m = idx >> 6;
    int d0 = (idx & 63) << 3;
    int t = m & (NT - 1);
    int bc = m >> 10;
    const float* xp = x + (size_t)bc * NL;
    int g0 = t * 256 + d0 - 128;
    float v[8];
    if (g0 >= 0 && g0 + 8 <= NL) {
        float4 u0 = *(const float4*)(xp + g0);
        float4 u1 = *(const float4*)(xp + g0 + 4);
        v[0] = u0.x; v[1] = u0.y; v[2] = u0.z; v[3] = u0.w;
        v[4] = u1.x; v[5] = u1.y; v[6] = u1.z; v[7] = u1.w;
    } else {
#pragma unroll
        for (int j = 0; j < 8; j++) {
            int g = g0 + j;
            v[j] = (g >= 0 && g < NL) ? xp[g] : 0.f;
        }
    }
    unsigned hw[4];
#pragma unroll
    for (int j = 0; j < 4; j++) {
        __half h0 = __float2half_rn(v[2 * j]);
        __half h1 = __float2half_rn(v[2 * j + 1]);
        hw[j] = (unsigned)__half_as_ushort(h0) |
                ((unsigned)__half_as_ushort(h1) << 16);
    }
    *(uint4*)(g_Ah + (size_t)m * KD + d0) = make_uint4(hw[0], hw[1], hw[2], hw[3]);
}

// ---------------------------------------------------------------------------
// spec_gemm: CTA tile 128(m) x 128(n), K=512 in 8 chunks, cp.async double buf.
// Single-pass fp16 mma.sync, fp32 accum. 8 warps 2(m)x4(n), warp 64x32.
// grid = (4 ntiles, 512 mtiles); 72 KB smem -> 2 CTAs/SM.
// ---------------------------------------------------------------------------
__global__ __launch_bounds__(256) void spec_gemm(float* __restrict__ P) {
    extern __shared__ char smem[];
    const unsigned sb = smem_u32(smem);
    const int tid = threadIdx.x;
    const int wid = tid >> 5, lane = tid & 31;
    const int warp_m = wid >> 2, warp_n = wid & 3;
    const int m0 = blockIdx.y * 128, n0 = blockIdx.x * 128;

    float d[4][4][4];
#pragma unroll
    for (int mi = 0; mi < 4; mi++)
#pragma unroll
        for (int ni = 0; ni < 4; ni++)
#pragma unroll
            for (int r = 0; r < 4; r++) d[mi][ni][r] = 0.f;

    const unsigned a_base = (unsigned)((warp_m * 64 + (lane & 15)) * ROWB +
                                       ((lane >> 4) << 4));
    // x4 B: lanes 0-7 n+0..7/seg0, 8-15 n+0..7/seg1, 16-23 n+8..15/seg0, 24-31 seg1
    const unsigned b_base = (unsigned)((warp_n * 32 + (lane & 7) +
                                        ((lane >> 4) << 3)) * ROWB +
                                       (((lane >> 3) & 1) << 4));

    auto stage = [&](int buf, int ch) {
        const int k0 = ch * KC;
#pragma unroll
        for (int rep = 0; rep < 8; rep++) {
            int i = rep * 256 + tid;         // 0..2047
            int tile = i >> 10, row = (i >> 3) & 127, seg = i & 7;
            const unsigned short* src =
                tile ? g_B + ((size_t)(n0 + row) * KD + k0)
                     : g_Ah + ((size_t)(m0 + row) * KD + k0);
            unsigned dst = sb + buf * BUFB + tile * TILEB + row * ROWB + seg * 16;
            CP16(dst, src + seg * 8);
        }
        CPCOMMIT();
    };

    stage(0, 0);
    for (int ch = 0; ch < 8; ch++) {
        const int buf = ch & 1;
        if (ch < 7) { stage(buf ^ 1, ch + 1); CPWAIT(1); }
        else        { CPWAIT(0); }
        __syncthreads();

        const unsigned abase = sb + buf * BUFB + T_A + a_base;
        const unsigned bbase = sb + buf * BUFB + T_B + b_base;
#pragma unroll
        for (int ks = 0; ks < 4; ks++) {
            unsigned a[4][4], bf[4][2];
#pragma unroll
            for (int mi = 0; mi < 4; mi++)
                ldsm4(a[mi], abase + mi * (16 * ROWB) + ks * 32);
#pragma unroll
            for (int nh = 0; nh < 2; nh++) {
                unsigned r[4];
                ldsm4(r, bbase + nh * (16 * ROWB) + ks * 32);
                bf[2 * nh][0] = r[0]; bf[2 * nh][1] = r[1];
                bf[2 * nh + 1][0] = r[2]; bf[2 * nh + 1][1] = r[3];
            }
#pragma unroll
            for (int mi = 0; mi < 4; mi++)
#pragma unroll
                for (int ni = 0; ni < 4; ni++)
                    mma_fp16(d[mi][ni], a[mi], bf[ni]);
        }
        __syncthreads();
    }

    // ---- epilogue: col pairs (re_f, im_f); f==0 pair is (re_0, re_256) ----
    float pmax = 0.f;
    const int fbase = (n0 >> 1) + warp_n * 16 + (lane & 3);
#pragma unroll
    for (int mi = 0; mi < 4; mi++) {
        int mrow = m0 + warp_m * 64 + mi * 16 + (lane >> 2);
#pragma unroll
        for (int h = 0; h < 2; h++) {
            int m = mrow + h * 8;
            int bc = m >> 10, t = m & (NT - 1);
#pragma unroll
            for (int ni = 0; ni < 4; ni++) {
                float re = d[mi][ni][2 * h];
                float im = d[mi][ni][2 * h + 1];
                int f = fbase + ni * 4;
                if (f == 0) {
                    // im slot carries re of Nyquist bin; true im_0 == 0
                    float p0 = fmaxf(re * re, AMINF);
                    float pn = fmaxf(im * im, AMINF);
                    pmax = fmaxf(pmax, fmaxf(p0, pn));
                    g_P[((size_t)bc * NF + 0) * NT + t] =
                        TEN_OVER_LOG2_10 * __log2f(p0);
                    g_P[((size_t)bc * NF + 256) * NT + t] =
                        TEN_OVER_LOG2_10 * __log2f(pn);
                } else {
                    float p = fmaxf(fmaf(re, re, im * im), AMINF);
                    pmax = fmaxf(pmax, p);
                    g_P[((size_t)bc * NF + f) * NT + t] =
                        TEN_OVER_LOG2_10 * __log2f(p);
                }
            }
        }
    }
#pragma unroll
    for (int o = 16; o; o >>= 1)
        pmax = fmaxf(pmax, __shfl_xor_sync(0xFFFFFFFFu, pmax, o));
    __shared__ float red[8];
    if (lane == 0) red[wid] = pmax;
    __syncthreads();
    if (tid == 0) {
        float mm = red[0];
#pragma unroll
        for (int w = 1; w < 8; w++) mm = fmaxf(mm, red[w]);
        atomicMax(&g_pmax, __float_as_uint(mm));
    }
}

// ---------------------------------------------------------------------------
// spec_fin: transpose-interleave g_P[bc][f][t] -> out[b][f][t][c], subtract
// global max, clamp. One block per (b,f) row; coalesced both sides.
// ---------------------------------------------------------------------------
__global__ void spec_fin(float* __restrict__ out) {
    const int bf = blockIdx.x;          // 0..32*257-1
    const int b = bf / NF, f = bf % NF;
    const float lmax =
        TEN_OVER_LOG2_10 * __log2f(fmaxf(__uint_as_float(g_pmax), AMINF));
    const float* s0 = g_P + ((size_t)(b * 2 + 0) * NF + f) * NT;
    const float* s1 = g_P + ((size_t)(b * 2 + 1) * NF + f) * NT;
    float2* orow = (float2*)(out + ((size_t)b * NF + f) * NT * NC);
#pragma unroll
    for (int j = 0; j < 4; j++) {
        int t = j * 256 + threadIdx.x;
        float2 v;
        v.x = fmaxf(s0[t] - lmax, -80.f);
        v.y = fmaxf(s1[t] - lmax, -80.f);
        orow[t] = v;
    }
}

extern "C" void kernel_launch(void* const* d_in, const int* in_sizes, int n_in,
                              void* d_out, int out_size) {
    const float* x = (const float*)d_in[0];
    const float* kre = (const float*)d_in[1];
    const float* kim = (const float*)d_in[2];
    float* out = (float*)d_out;

    cudaFuncSetAttribute(spec_gemm, cudaFuncAttributeMaxDynamicSharedMemorySize,
                         SMEM_TOTAL);

    prep_B<<<1024, 256>>>(kre, kim);
    prep_A<<<16384, 256>>>(x);

    float* P;
    cudaGetSymbolAddress((void**)&P, g_P);
    spec_gemm<<<dim3(4, MFR / 128), 256, SMEM_TOTAL>>>(P);
    spec_fin<<<NB * NF, 256>>>(out);
}